// round 1
// baseline (speedup 1.0000x reference)
#include <cuda_runtime.h>
#include <cstdint>

#define N_NODES 100000
#define N_EDGES 1600000
#define F0 128
#define F1 48
#define F2 32

// ---------------- scratch (static device globals; no allocation) ----------------
__device__ int   g_flag32;
__device__ int   g_src[N_EDGES];
__device__ int   g_dst[N_EDGES];
__device__ int   g_deg[N_NODES];
__device__ float g_dis[N_NODES];
__device__ float g_h1[(size_t)N_NODES * F1];    // x @ W1
__device__ float g_agg1[(size_t)N_NODES * F1];  // aggregated layer-1
__device__ float g_h2[(size_t)N_NODES * F2];    // relu(agg1+b1) @ W2

// vectorized fire-and-forget atomic add (sm_90+): 4 floats / op
__device__ __forceinline__ void red_add4(float* p, float4 v) {
    asm volatile("red.global.add.v4.f32 [%0], {%1, %2, %3, %4};"
                 :: "l"(p), "f"(v.x), "f"(v.y), "f"(v.z), "f"(v.w)
                 : "memory");
}

// ---------------- edge-index dtype detection + conversion ----------------
__global__ void detect_kernel(const void* ei) {
    if (threadIdx.x == 0 && blockIdx.x == 0) {
        const long long* p = (const long long*)ei;
        int is32 = 0;
        for (int i = 0; i < 256; i++) {
            unsigned long long v = (unsigned long long)p[i];
            if (v >= (unsigned long long)N_NODES) { is32 = 1; break; }
        }
        g_flag32 = is32;
    }
}

__global__ void convert_kernel(const void* ei) {
    int e = blockIdx.x * blockDim.x + threadIdx.x;
    if (e >= N_EDGES) return;
    if (g_flag32) {
        const int* p = (const int*)ei;
        g_src[e] = p[e];
        g_dst[e] = p[N_EDGES + e];
    } else {
        const long long* p = (const long long*)ei;
        g_src[e] = (int)p[e];
        g_dst[e] = (int)p[N_EDGES + e];
    }
}

// ---------------- degree / normalization ----------------
__global__ void deg_init_kernel() {
    int i = blockIdx.x * blockDim.x + threadIdx.x;
    if (i < N_NODES) g_deg[i] = 1;  // self-loop
}

__global__ void deg_count_kernel() {
    int e = blockIdx.x * blockDim.x + threadIdx.x;
    if (e < N_EDGES) atomicAdd(&g_deg[g_dst[e]], 1);
}

__global__ void dis_kernel() {
    int i = blockIdx.x * blockDim.x + threadIdx.x;
    if (i < N_NODES) g_dis[i] = rsqrtf((float)g_deg[i]);
}

// ---------------- GEMM1: h1 = x @ W1; agg1 init = h1 * dis^2 (self-loop) ----------------
// 128 threads/block, 32 rows/block; per-thread 4 rows x 3 cols register tile.
__global__ __launch_bounds__(128) void gemm1_kernel(const float* __restrict__ x,
                                                    const float* __restrict__ W1) {
    __shared__ float xs[32][132];   // padded: stride%32 = 4 -> row-distinct banks
    __shared__ float ws[48][129];   // W1 transposed [c][k], pad -> conflict-free

    int tid = threadIdx.x;
    int row0 = blockIdx.x * 32;

    for (int idx = tid; idx < F0 * F1; idx += 128) {
        int k = idx / F1, c = idx % F1;  // W1 row-major [128][48]
        ws[c][k] = W1[idx];
    }
    for (int idx = tid; idx < 32 * F0; idx += 128) {
        int r = idx >> 7, c = idx & 127;
        int row = row0 + r;
        xs[r][c] = (row < N_NODES) ? x[(size_t)row * F0 + c] : 0.0f;
    }
    __syncthreads();

    int tc = tid & 15;
    int tr = tid >> 4;  // 0..7  -> rows tr*4 .. tr*4+3

    float acc[4][3];
#pragma unroll
    for (int i = 0; i < 4; i++)
#pragma unroll
        for (int j = 0; j < 3; j++) acc[i][j] = 0.0f;

#pragma unroll 4
    for (int k = 0; k < F0; k++) {
        float w0 = ws[tc][k];
        float w1 = ws[tc + 16][k];
        float w2 = ws[tc + 32][k];
#pragma unroll
        for (int i = 0; i < 4; i++) {
            float a = xs[tr * 4 + i][k];
            acc[i][0] += a * w0;
            acc[i][1] += a * w1;
            acc[i][2] += a * w2;
        }
    }

#pragma unroll
    for (int i = 0; i < 4; i++) {
        int row = row0 + tr * 4 + i;
        if (row < N_NODES) {
            float d = g_dis[row];
            float sn = d * d;  // self-loop norm = 1/deg
#pragma unroll
            for (int j = 0; j < 3; j++) {
                int c = tc + 16 * j;
                float v = acc[i][j];
                g_h1[(size_t)row * F1 + c] = v;
                g_agg1[(size_t)row * F1 + c] = v * sn;
            }
        }
    }
}

// ---------------- scatter layer 1: agg1[dst] += h1[src] * dis[src]*dis[dst] ----------------
__global__ void scatter1_kernel() {
    int e = blockIdx.x * blockDim.x + threadIdx.x;
    if (e >= N_EDGES) return;
    int s = g_src[e];
    int d = g_dst[e];
    float nrm = g_dis[s] * g_dis[d];
    const float4* hp = reinterpret_cast<const float4*>(g_h1 + (size_t)s * F1);
    float* ap = g_agg1 + (size_t)d * F1;
#pragma unroll
    for (int j = 0; j < F1 / 4; j++) {
        float4 v = hp[j];
        v.x *= nrm; v.y *= nrm; v.z *= nrm; v.w *= nrm;
        red_add4(ap + 4 * j, v);
    }
}

// ---------------- mid: z1 = relu(agg1+b1); h2 = z1@W2; out init = h2*dis^2 + b2 ----------------
// one warp per row; 8 rows per 256-thread block
__global__ __launch_bounds__(256) void mid_kernel(const float* __restrict__ b1,
                                                  const float* __restrict__ W2,
                                                  const float* __restrict__ b2,
                                                  float* __restrict__ out) {
    __shared__ float ws2[32][49];  // W2 transposed [c][k], padded
    __shared__ float zs[8][48];

    int tid = threadIdx.x;
    for (int idx = tid; idx < F1 * F2; idx += 256) {
        int k = idx / F2, c = idx % F2;  // W2 row-major [48][32]
        ws2[c][k] = W2[idx];
    }
    __syncthreads();

    int w = tid >> 5, lane = tid & 31;
    int row = blockIdx.x * 8 + w;
    if (row >= N_NODES) return;

    const float* ag = g_agg1 + (size_t)row * F1;
    zs[w][lane] = fmaxf(ag[lane] + b1[lane], 0.0f);
    if (lane < 16) zs[w][32 + lane] = fmaxf(ag[32 + lane] + b1[32 + lane], 0.0f);
    __syncwarp();

    float acc = 0.0f;
#pragma unroll
    for (int k = 0; k < F1; k++) acc += zs[w][k] * ws2[lane][k];

    float d = g_dis[row];
    g_h2[(size_t)row * F2 + lane] = acc;
    out[(size_t)row * F2 + lane] = acc * d * d + b2[lane];
}

// ---------------- scatter layer 2: out[dst] += h2[src] * dis[src]*dis[dst] ----------------
__global__ void scatter2_kernel(float* __restrict__ out) {
    int e = blockIdx.x * blockDim.x + threadIdx.x;
    if (e >= N_EDGES) return;
    int s = g_src[e];
    int d = g_dst[e];
    float nrm = g_dis[s] * g_dis[d];
    const float4* hp = reinterpret_cast<const float4*>(g_h2 + (size_t)s * F2);
    float* op = out + (size_t)d * F2;
#pragma unroll
    for (int j = 0; j < F2 / 4; j++) {
        float4 v = hp[j];
        v.x *= nrm; v.y *= nrm; v.z *= nrm; v.w *= nrm;
        red_add4(op + 4 * j, v);
    }
}

// ---------------- launch ----------------
extern "C" void kernel_launch(void* const* d_in, const int* in_sizes, int n_in,
                              void* d_out, int out_size) {
    const float* x  = (const float*)d_in[0];
    const void*  ei = d_in[1];
    const float* W1 = (const float*)d_in[2];
    const float* b1 = (const float*)d_in[3];
    const float* W2 = (const float*)d_in[4];
    const float* b2 = (const float*)d_in[5];
    float* out = (float*)d_out;

    detect_kernel<<<1, 32>>>(ei);
    convert_kernel<<<(N_EDGES + 255) / 256, 256>>>(ei);
    deg_init_kernel<<<(N_NODES + 255) / 256, 256>>>();
    deg_count_kernel<<<(N_EDGES + 255) / 256, 256>>>();
    dis_kernel<<<(N_NODES + 255) / 256, 256>>>();
    gemm1_kernel<<<(N_NODES + 31) / 32, 128>>>(x, W1);
    scatter1_kernel<<<(N_EDGES + 255) / 256, 256>>>();
    mid_kernel<<<(N_NODES + 7) / 8, 256>>>(b1, W2, b2, out);
    scatter2_kernel<<<(N_EDGES + 255) / 256, 256>>>(out);
}

// round 2
// speedup vs baseline: 1.6759x; 1.6759x over previous
#include <cuda_runtime.h>
#include <cstdint>

#define N_NODES 100000
#define N_EDGES 1600000
#define F0 128
#define F1 48
#define F2 32
#define SCAN_B 1024
#define N_SCAN_BLK ((N_NODES + SCAN_B - 1) / SCAN_B)   // 98

// ---------------- scratch (static device globals; no allocation) ----------------
__device__ int    g_flag32;
__device__ int    g_src[N_EDGES];
__device__ int    g_dst[N_EDGES];
__device__ int    g_deg[N_NODES];        // edge-only indegree
__device__ int    g_scan[N_NODES];       // inclusive per-block scan
__device__ int    g_bsum[N_SCAN_BLK];
__device__ int    g_boff[N_SCAN_BLK];
__device__ int    g_rowstart[N_NODES];
__device__ int    g_cursor[N_NODES];
__device__ float  g_dis[N_NODES];
__device__ float2 g_edge[N_EDGES];       // (src-as-bits, norm) in CSR order
__device__ float  g_h1[(size_t)N_NODES * F1];
__device__ float  g_h2[(size_t)N_NODES * F2];

// ---------------- init: zero deg + dtype detect ----------------
__global__ void init_kernel(const void* ei) {
    int i = blockIdx.x * blockDim.x + threadIdx.x;
    if (i < N_NODES) g_deg[i] = 0;
    if (i == 0) {
        const long long* p = (const long long*)ei;
        int is32 = 0;
        for (int k = 0; k < 256; k++) {
            unsigned long long v = (unsigned long long)p[k];
            if (v >= (unsigned long long)N_NODES) { is32 = 1; break; }
        }
        g_flag32 = is32;
    }
}

// ---------------- convert to int32 + degree histogram ----------------
__global__ void convert_count_kernel(const void* ei) {
    int e = blockIdx.x * blockDim.x + threadIdx.x;
    if (e >= N_EDGES) return;
    int s, d;
    if (g_flag32) {
        const int* p = (const int*)ei;
        s = p[e]; d = p[N_EDGES + e];
    } else {
        const long long* p = (const long long*)ei;
        s = (int)p[e]; d = (int)p[N_EDGES + e];
    }
    g_src[e] = s;
    g_dst[e] = d;
    atomicAdd(&g_deg[d], 1);
}

// ---------------- prefix scan of deg (3 kernels) ----------------
__global__ __launch_bounds__(SCAN_B) void scan1_kernel() {
    __shared__ int s[SCAN_B];
    int t = threadIdx.x;
    int i = blockIdx.x * SCAN_B + t;
    int v = (i < N_NODES) ? g_deg[i] : 0;
    s[t] = v;
    __syncthreads();
    for (int ofs = 1; ofs < SCAN_B; ofs <<= 1) {
        int add = (t >= ofs) ? s[t - ofs] : 0;
        __syncthreads();
        s[t] += add;
        __syncthreads();
    }
    if (i < N_NODES) g_scan[i] = s[t];
    if (t == SCAN_B - 1) g_bsum[blockIdx.x] = s[t];
}

__global__ void scan2_kernel() {
    __shared__ int s[128];
    int t = threadIdx.x;
    int v = (t < N_SCAN_BLK) ? g_bsum[t] : 0;
    s[t] = v;
    __syncthreads();
    for (int ofs = 1; ofs < 128; ofs <<= 1) {
        int add = (t >= ofs) ? s[t - ofs] : 0;
        __syncthreads();
        s[t] += add;
        __syncthreads();
    }
    if (t < N_SCAN_BLK) g_boff[t] = s[t] - v;   // exclusive
}

__global__ void scan3_kernel() {
    int i = blockIdx.x * blockDim.x + threadIdx.x;
    if (i >= N_NODES) return;
    int deg = g_deg[i];
    int rs = g_scan[i] - deg + g_boff[i / SCAN_B];
    g_rowstart[i] = rs;
    g_cursor[i] = rs;
    g_dis[i] = rsqrtf((float)(deg + 1));        // +1 self-loop
}

// ---------------- bucket edges into CSR order with precomputed norm ----------------
__global__ void csr_scatter_kernel() {
    int e = blockIdx.x * blockDim.x + threadIdx.x;
    if (e >= N_EDGES) return;
    int s = g_src[e];
    int d = g_dst[e];
    int pos = atomicAdd(&g_cursor[d], 1);
    g_edge[pos] = make_float2(__int_as_float(s), g_dis[s] * g_dis[d]);
}

// ---------------- GEMM1: h1 = x @ W1 ----------------
__global__ __launch_bounds__(128) void gemm1_kernel(const float* __restrict__ x,
                                                    const float* __restrict__ W1) {
    __shared__ float xs[32][132];
    __shared__ float ws[48][129];

    int tid = threadIdx.x;
    int row0 = blockIdx.x * 32;

    for (int idx = tid; idx < F0 * F1; idx += 128) {
        int k = idx / F1, c = idx % F1;
        ws[c][k] = W1[idx];
    }
    for (int idx = tid; idx < 32 * F0; idx += 128) {
        int r = idx >> 7, c = idx & 127;
        int row = row0 + r;
        xs[r][c] = (row < N_NODES) ? x[(size_t)row * F0 + c] : 0.0f;
    }
    __syncthreads();

    int tc = tid & 15;
    int tr = tid >> 4;

    float acc[4][3];
#pragma unroll
    for (int i = 0; i < 4; i++)
#pragma unroll
        for (int j = 0; j < 3; j++) acc[i][j] = 0.0f;

#pragma unroll 4
    for (int k = 0; k < F0; k++) {
        float w0 = ws[tc][k];
        float w1 = ws[tc + 16][k];
        float w2 = ws[tc + 32][k];
#pragma unroll
        for (int i = 0; i < 4; i++) {
            float a = xs[tr * 4 + i][k];
            acc[i][0] += a * w0;
            acc[i][1] += a * w1;
            acc[i][2] += a * w2;
        }
    }

#pragma unroll
    for (int i = 0; i < 4; i++) {
        int row = row0 + tr * 4 + i;
        if (row < N_NODES) {
#pragma unroll
            for (int j = 0; j < 3; j++)
                g_h1[(size_t)row * F1 + tc + 16 * j] = acc[i][j];
        }
    }
}

// ---------------- layer-1 gather + bias + ReLU + GEMM2 fused -> h2 ----------------
// one warp per node; 8 warps / 256-thread block
__global__ __launch_bounds__(256) void agg1_mid_kernel(const float* __restrict__ b1,
                                                       const float* __restrict__ W2) {
    __shared__ float ws2[32][49];   // W2^T [c][k], padded (49,32 coprime -> conflict-free)
    __shared__ float zs[8][48];

    int tid = threadIdx.x;
    for (int idx = tid; idx < F1 * F2; idx += 256) {
        int k = idx / F2, c = idx % F2;
        ws2[c][k] = W2[idx];
    }
    __syncthreads();

    int w = tid >> 5, lane = tid & 31;
    int row = blockIdx.x * 8 + w;
    if (row >= N_NODES) return;

    float dself = g_dis[row];
    float sn = dself * dself;
    const float* hrow = g_h1 + (size_t)row * F1;
    float acc0 = sn * hrow[lane];
    float acc1 = (lane < 16) ? sn * hrow[32 + lane] : 0.0f;

    int rs = g_rowstart[row];
    int re = rs + g_deg[row];
#pragma unroll 2
    for (int e = rs; e < re; e++) {
        float2 ed = g_edge[e];
        int s = __float_as_int(ed.x);
        float nrm = ed.y;
        const float* hp = g_h1 + (size_t)s * F1;
        acc0 += nrm * __ldg(hp + lane);
        if (lane < 16) acc1 += nrm * __ldg(hp + 32 + lane);
    }

    // bias + relu -> z in smem
    zs[w][lane] = fmaxf(acc0 + b1[lane], 0.0f);
    if (lane < 16) zs[w][32 + lane] = fmaxf(acc1 + b1[32 + lane], 0.0f);
    __syncwarp();

    // h2[row][lane] = sum_k z[k] * W2[k][lane]
    float h = 0.0f;
#pragma unroll
    for (int k = 0; k < F1; k++) h += zs[w][k] * ws2[lane][k];
    g_h2[(size_t)row * F2 + lane] = h;
}

// ---------------- layer-2 gather + bias -> out ----------------
__global__ __launch_bounds__(256) void agg2_kernel(const float* __restrict__ b2,
                                                   float* __restrict__ out) {
    int tid = threadIdx.x;
    int w = tid >> 5, lane = tid & 31;
    int row = blockIdx.x * 8 + w;
    if (row >= N_NODES) return;

    float dself = g_dis[row];
    float acc = dself * dself * g_h2[(size_t)row * F2 + lane];

    int rs = g_rowstart[row];
    int re = rs + g_deg[row];
#pragma unroll 2
    for (int e = rs; e < re; e++) {
        float2 ed = g_edge[e];
        int s = __float_as_int(ed.x);
        acc += ed.y * __ldg(g_h2 + (size_t)s * F2 + lane);
    }
    out[(size_t)row * F2 + lane] = acc + b2[lane];
}

// ---------------- launch ----------------
extern "C" void kernel_launch(void* const* d_in, const int* in_sizes, int n_in,
                              void* d_out, int out_size) {
    const float* x  = (const float*)d_in[0];
    const void*  ei = d_in[1];
    const float* W1 = (const float*)d_in[2];
    const float* b1 = (const float*)d_in[3];
    const float* W2 = (const float*)d_in[4];
    const float* b2 = (const float*)d_in[5];
    float* out = (float*)d_out;

    init_kernel<<<(N_NODES + 255) / 256, 256>>>(ei);
    convert_count_kernel<<<(N_EDGES + 255) / 256, 256>>>(ei);
    scan1_kernel<<<N_SCAN_BLK, SCAN_B>>>();
    scan2_kernel<<<1, 128>>>();
    scan3_kernel<<<(N_NODES + 255) / 256, 256>>>();
    csr_scatter_kernel<<<(N_EDGES + 255) / 256, 256>>>();
    gemm1_kernel<<<(N_NODES + 31) / 32, 128>>>(x, W1);
    agg1_mid_kernel<<<(N_NODES + 7) / 8, 256>>>(b1, W2);
    agg2_kernel<<<(N_NODES + 7) / 8, 256>>>(b2, out);
}

// round 3
// speedup vs baseline: 1.8250x; 1.0889x over previous
#include <cuda_runtime.h>
#include <cstdint>

#define N_NODES 100000
#define N_EDGES 1600000
#define F0 128
#define F1 48
#define F2 32
#define SCAN_B 1024
#define N_SCAN_BLK ((N_NODES + SCAN_B - 1) / SCAN_B)   // 98

// ---------------- scratch (static device globals; no allocation) ----------------
__device__ int    g_flag32;
__device__ int    g_deg[N_NODES];
__device__ int    g_bflag[N_SCAN_BLK];     // lookback: 0 = not ready, else blocksum+1
__device__ int    g_rowstart[N_NODES];
__device__ int    g_cursor[N_NODES];
__device__ float  g_dis[N_NODES];
__device__ __align__(16) float2 g_edge[N_EDGES];   // (src-as-bits, norm) CSR order
__device__ __align__(16) float  g_h1[(size_t)N_NODES * F1];
__device__ __align__(16) float  g_h2[(size_t)N_NODES * F2];

// ---------------- init: zero deg + flags, dtype detect ----------------
__global__ void init_kernel(const void* ei) {
    int i = blockIdx.x * blockDim.x + threadIdx.x;
    if (i < N_NODES) g_deg[i] = 0;
    if (i < N_SCAN_BLK) g_bflag[i] = 0;
    if (i == 0) {
        const long long* p = (const long long*)ei;
        int is32 = 0;
        for (int k = 0; k < 256; k++) {
            unsigned long long v = (unsigned long long)p[k];
            if (v >= (unsigned long long)N_NODES) { is32 = 1; break; }
        }
        g_flag32 = is32;
    }
}

// ---------------- degree histogram (reads edge_index directly) ----------------
__global__ void count_kernel(const void* ei) {
    int e = blockIdx.x * blockDim.x + threadIdx.x;
    if (e >= N_EDGES) return;
    int d;
    if (g_flag32) d = ((const int*)ei)[N_EDGES + e];
    else          d = (int)((const long long*)ei)[N_EDGES + e];
    atomicAdd(&g_deg[d], 1);
}

// ---------------- fused scan: rowstart/cursor/dis in ONE kernel ----------------
__global__ __launch_bounds__(SCAN_B) void scan_kernel() {
    __shared__ int s[SCAN_B];
    __shared__ int s_ex;
    int t = threadIdx.x, b = blockIdx.x;
    int i = b * SCAN_B + t;
    int deg = (i < N_NODES) ? g_deg[i] : 0;
    s[t] = deg;
    __syncthreads();
    for (int ofs = 1; ofs < SCAN_B; ofs <<= 1) {
        int add = (t >= ofs) ? s[t - ofs] : 0;
        __syncthreads();
        s[t] += add;
        __syncthreads();
    }
    // publish this block's total (value+1, so nonzero == ready; no separate fence needed)
    if (t == SCAN_B - 1)
        *(volatile int*)&g_bflag[b] = s[SCAN_B - 1] + 1;
    // warp 0: sum all earlier block totals (blocks publish before any waiting -> no deadlock)
    if (t < 32) {
        int sum = 0;
        for (int j = t; j < b; j += 32) {
            int v;
            while ((v = *(volatile int*)&g_bflag[j]) == 0) { }
            sum += v - 1;
        }
#pragma unroll
        for (int o = 16; o; o >>= 1) sum += __shfl_down_sync(0xffffffffu, sum, o);
        if (t == 0) s_ex = sum;
    }
    __syncthreads();
    if (i < N_NODES) {
        int rs = s_ex + s[t] - deg;   // exclusive prefix
        g_rowstart[i] = rs;
        g_cursor[i] = rs;
        g_dis[i] = rsqrtf((float)(deg + 1));   // +1 self-loop
    }
}

// ---------------- bucket edges into CSR order with precomputed norm ----------------
__global__ void csr_scatter_kernel(const void* ei) {
    int e = blockIdx.x * blockDim.x + threadIdx.x;
    if (e >= N_EDGES) return;
    int s, d;
    if (g_flag32) {
        const int* p = (const int*)ei;
        s = p[e]; d = p[N_EDGES + e];
    } else {
        const long long* p = (const long long*)ei;
        s = (int)p[e]; d = (int)p[N_EDGES + e];
    }
    int pos = atomicAdd(&g_cursor[d], 1);
    g_edge[pos] = make_float2(__int_as_float(s), g_dis[s] * g_dis[d]);
}

// ---------------- GEMM1: h1 = x @ W1 (runs on side stream, overlapped) ----------------
__global__ __launch_bounds__(128) void gemm1_kernel(const float* __restrict__ x,
                                                    const float* __restrict__ W1) {
    __shared__ float xs[32][132];
    __shared__ float ws[48][129];

    int tid = threadIdx.x;
    int row0 = blockIdx.x * 32;

    for (int idx = tid; idx < F0 * F1; idx += 128) {
        int k = idx / F1, c = idx % F1;
        ws[c][k] = W1[idx];
    }
    for (int idx = tid; idx < 32 * F0; idx += 128) {
        int r = idx >> 7, c = idx & 127;
        int row = row0 + r;
        xs[r][c] = (row < N_NODES) ? x[(size_t)row * F0 + c] : 0.0f;
    }
    __syncthreads();

    int tc = tid & 15;
    int tr = tid >> 4;

    float acc[4][3];
#pragma unroll
    for (int i = 0; i < 4; i++)
#pragma unroll
        for (int j = 0; j < 3; j++) acc[i][j] = 0.0f;

#pragma unroll 4
    for (int k = 0; k < F0; k++) {
        float w0 = ws[tc][k];
        float w1 = ws[tc + 16][k];
        float w2 = ws[tc + 32][k];
#pragma unroll
        for (int i = 0; i < 4; i++) {
            float a = xs[tr * 4 + i][k];
            acc[i][0] += a * w0;
            acc[i][1] += a * w1;
            acc[i][2] += a * w2;
        }
    }

#pragma unroll
    for (int i = 0; i < 4; i++) {
        int row = row0 + tr * 4 + i;
        if (row < N_NODES) {
#pragma unroll
            for (int j = 0; j < 3; j++)
                g_h1[(size_t)row * F1 + tc + 16 * j] = acc[i][j];
        }
    }
}

// ---------------- layer-1 gather + bias/relu + block-GEMM2 -> h2 ----------------
// 256 threads, 128 nodes per block. Phase 1: warp-per-node gather (16 nodes/warp,
// 24-lane float2 vector loads). Phase 2: block-cooperative GEMM2 with 4x4 tiles.
#define A1_NODES 128
__global__ __launch_bounds__(256) void agg1_mid_kernel(const float* __restrict__ b1,
                                                       const float* __restrict__ W2) {
    __shared__ __align__(16) float zs[A1_NODES][50];   // relu(agg1+b1), padded
    __shared__ __align__(16) float ws2t[48][36];       // W2 [k][c], padded

    int tid = threadIdx.x;
    for (int idx = tid; idx < F1 * F2; idx += 256) {
        int k = idx >> 5, c = idx & 31;
        ws2t[k][c] = W2[idx];
    }

    int w = tid >> 5, lane = tid & 31;
    int base = blockIdx.x * A1_NODES;

    float2 b1v = make_float2(0.f, 0.f);
    if (lane < 24) b1v = ((const float2*)b1)[lane];

    // ---- phase 1: gather 16 nodes per warp ----
    for (int i = 0; i < 16; i++) {
        int r = w * 16 + i;
        int node = base + r;
        if (node < N_NODES) {
            float2 acc = make_float2(0.f, 0.f);
            if (lane < 24) {
                float ds = g_dis[node];
                float sn = ds * ds;
                float2 hv = ((const float2*)(g_h1 + (size_t)node * F1))[lane];
                acc.x = sn * hv.x;
                acc.y = sn * hv.y;

                int rs = g_rowstart[node];
                int re = rs + g_deg[node];
                int e = rs;
                for (; e + 4 <= re; e += 4) {
                    float2 e0 = g_edge[e + 0];
                    float2 e1 = g_edge[e + 1];
                    float2 e2 = g_edge[e + 2];
                    float2 e3 = g_edge[e + 3];
                    float2 v0 = ((const float2*)(g_h1 + (size_t)__float_as_int(e0.x) * F1))[lane];
                    float2 v1 = ((const float2*)(g_h1 + (size_t)__float_as_int(e1.x) * F1))[lane];
                    float2 v2 = ((const float2*)(g_h1 + (size_t)__float_as_int(e2.x) * F1))[lane];
                    float2 v3 = ((const float2*)(g_h1 + (size_t)__float_as_int(e3.x) * F1))[lane];
                    acc.x += e0.y * v0.x; acc.y += e0.y * v0.y;
                    acc.x += e1.y * v1.x; acc.y += e1.y * v1.y;
                    acc.x += e2.y * v2.x; acc.y += e2.y * v2.y;
                    acc.x += e3.y * v3.x; acc.y += e3.y * v3.y;
                }
                for (; e < re; e++) {
                    float2 ed = g_edge[e];
                    float2 v = ((const float2*)(g_h1 + (size_t)__float_as_int(ed.x) * F1))[lane];
                    acc.x += ed.y * v.x;
                    acc.y += ed.y * v.y;
                }
                // bias + relu -> smem
                zs[r][2 * lane]     = fmaxf(acc.x + b1v.x, 0.0f);
                zs[r][2 * lane + 1] = fmaxf(acc.y + b1v.y, 0.0f);
            }
        } else if (lane < 24) {
            zs[r][2 * lane] = 0.0f;
            zs[r][2 * lane + 1] = 0.0f;
        }
    }
    __syncthreads();

    // ---- phase 2: h2[r][c] = sum_k zs[r][k] * W2[k][c] ; 4 nodes x 4 cols per thread ----
    int ng = tid >> 3;          // 0..31 -> nodes ng*4 .. ng*4+3
    int cg = tid & 7;           // 0..7  -> cols  cg*4 .. cg*4+3
    int r0 = ng * 4;
    int c0 = cg * 4;

    float acc[4][4];
#pragma unroll
    for (int i = 0; i < 4; i++)
#pragma unroll
        for (int j = 0; j < 4; j++) acc[i][j] = 0.0f;

#pragma unroll 4
    for (int k = 0; k < F1; k++) {
        float4 wv = *(const float4*)&ws2t[k][c0];
        float z0 = zs[r0 + 0][k];
        float z1 = zs[r0 + 1][k];
        float z2 = zs[r0 + 2][k];
        float z3 = zs[r0 + 3][k];
        acc[0][0] += z0 * wv.x; acc[0][1] += z0 * wv.y; acc[0][2] += z0 * wv.z; acc[0][3] += z0 * wv.w;
        acc[1][0] += z1 * wv.x; acc[1][1] += z1 * wv.y; acc[1][2] += z1 * wv.z; acc[1][3] += z1 * wv.w;
        acc[2][0] += z2 * wv.x; acc[2][1] += z2 * wv.y; acc[2][2] += z2 * wv.z; acc[2][3] += z2 * wv.w;
        acc[3][0] += z3 * wv.x; acc[3][1] += z3 * wv.y; acc[3][2] += z3 * wv.z; acc[3][3] += z3 * wv.w;
    }

#pragma unroll
    for (int i = 0; i < 4; i++) {
        int node = base + r0 + i;
        if (node < N_NODES) {
            float4 hv = make_float4(acc[i][0], acc[i][1], acc[i][2], acc[i][3]);
            *(float4*)(g_h2 + (size_t)node * F2 + c0) = hv;
        }
    }
}

// ---------------- layer-2 gather + bias -> out ----------------
__global__ __launch_bounds__(256) void agg2_kernel(const float* __restrict__ b2,
                                                   float* __restrict__ out) {
    int tid = threadIdx.x;
    int w = tid >> 5, lane = tid & 31;
    int row = blockIdx.x * 8 + w;
    if (row >= N_NODES) return;

    float ds = g_dis[row];
    float acc = ds * ds * g_h2[(size_t)row * F2 + lane];

    int rs = g_rowstart[row];
    int re = rs + g_deg[row];
    int e = rs;
    for (; e + 4 <= re; e += 4) {
        float2 e0 = g_edge[e + 0];
        float2 e1 = g_edge[e + 1];
        float2 e2 = g_edge[e + 2];
        float2 e3 = g_edge[e + 3];
        float v0 = __ldg(g_h2 + (size_t)__float_as_int(e0.x) * F2 + lane);
        float v1 = __ldg(g_h2 + (size_t)__float_as_int(e1.x) * F2 + lane);
        float v2 = __ldg(g_h2 + (size_t)__float_as_int(e2.x) * F2 + lane);
        float v3 = __ldg(g_h2 + (size_t)__float_as_int(e3.x) * F2 + lane);
        acc += e0.y * v0 + e1.y * v1 + e2.y * v2 + e3.y * v3;
    }
    for (; e < re; e++) {
        float2 ed = g_edge[e];
        acc += ed.y * __ldg(g_h2 + (size_t)__float_as_int(ed.x) * F2 + lane);
    }
    out[(size_t)row * F2 + lane] = acc + b2[lane];
}

// ---------------- launch: fork gemm1 onto a side stream to overlap CSR build ----------------
extern "C" void kernel_launch(void* const* d_in, const int* in_sizes, int n_in,
                              void* d_out, int out_size) {
    const float* x  = (const float*)d_in[0];
    const void*  ei = d_in[1];
    const float* W1 = (const float*)d_in[2];
    const float* b1 = (const float*)d_in[3];
    const float* W2 = (const float*)d_in[4];
    const float* b2 = (const float*)d_in[5];
    float* out = (float*)d_out;

    cudaStream_t s2;
    cudaStreamCreateWithFlags(&s2, cudaStreamNonBlocking);
    cudaEvent_t evRoot, evG;
    cudaEventCreateWithFlags(&evRoot, cudaEventDisableTiming);
    cudaEventCreateWithFlags(&evG, cudaEventDisableTiming);

    // fork: gemm1 depends only on x/W1
    cudaEventRecord(evRoot, 0);
    cudaStreamWaitEvent(s2, evRoot, 0);
    gemm1_kernel<<<(N_NODES + 31) / 32, 128, 0, s2>>>(x, W1);
    cudaEventRecord(evG, s2);

    // main chain: CSR build
    init_kernel<<<(N_NODES + 255) / 256, 256>>>(ei);
    count_kernel<<<(N_EDGES + 255) / 256, 256>>>(ei);
    scan_kernel<<<N_SCAN_BLK, SCAN_B>>>();
    csr_scatter_kernel<<<(N_EDGES + 255) / 256, 256>>>(ei);

    // join, then the two gather stages
    cudaStreamWaitEvent(0, evG, 0);
    agg1_mid_kernel<<<(N_NODES + A1_NODES - 1) / A1_NODES, 256>>>(b1, W2);
    agg2_kernel<<<(N_NODES + 7) / 8, 256>>>(b2, out);
    // note: stream/events intentionally not destroyed here — kernel_launch is only
    // invoked a bounded number of times (correctness + capture), and destroying
    // capture-participating resources mid-capture is unsafe.
}

// round 4
// speedup vs baseline: 2.0879x; 1.1441x over previous
#include <cuda_runtime.h>
#include <cstdint>

#define N_NODES 100000
#define N_EDGES 1600000
#define F0 128
#define F1 48
#define F2 32
#define SCAN_B 1024
#define N_SCAN_BLK ((N_NODES + SCAN_B - 1) / SCAN_B)   // 98

// ---------------- scratch (static device globals; no allocation) ----------------
__device__ int    g_flag32;
__device__ int    g_deg[N_NODES];
__device__ int    g_bflag[N_SCAN_BLK];     // lookback: 0 = not ready, else blocksum+1
__device__ int    g_rowstart[N_NODES];
__device__ int    g_cursor[N_NODES];
__device__ float  g_dis[N_NODES];
__device__ __align__(16) float2 g_edge[N_EDGES];   // (src-as-bits, norm) CSR order
__device__ __align__(16) float  g_h1[(size_t)N_NODES * F1];
__device__ __align__(16) float  g_h2[(size_t)N_NODES * F2];

// ---------------- init: zero deg + flags, dtype detect ----------------
__global__ void init_kernel(const void* ei) {
    int i = blockIdx.x * blockDim.x + threadIdx.x;
    if (i < N_NODES) g_deg[i] = 0;
    if (i < N_SCAN_BLK) g_bflag[i] = 0;
    if (i == 0) {
        const long long* p = (const long long*)ei;
        int is32 = 0;
        for (int k = 0; k < 256; k++) {
            unsigned long long v = (unsigned long long)p[k];
            if (v >= (unsigned long long)N_NODES) { is32 = 1; break; }
        }
        g_flag32 = is32;
    }
}

// ---------------- degree histogram: 2 edges/thread, vector loads ----------------
__global__ void count_kernel(const void* ei) {
    int t = blockIdx.x * blockDim.x + threadIdx.x;
    int e = t * 2;
    if (e >= N_EDGES) return;
    int d0, d1;
    if (g_flag32) {
        int2 dd = *(const int2*)((const int*)ei + N_EDGES + e);
        d0 = dd.x; d1 = dd.y;
    } else {
        longlong2 dd = *(const longlong2*)((const long long*)ei + N_EDGES + e);
        d0 = (int)dd.x; d1 = (int)dd.y;
    }
    atomicAdd(&g_deg[d0], 1);
    atomicAdd(&g_deg[d1], 1);
}

// ---------------- fused scan: shfl warp-scan + single-warp block scan ----------------
__global__ __launch_bounds__(SCAN_B) void scan_kernel() {
    __shared__ int wsum[32];
    __shared__ int s_ex;
    int t = threadIdx.x, b = blockIdx.x;
    int i = b * SCAN_B + t;
    int deg = (i < N_NODES) ? g_deg[i] : 0;
    int lane = t & 31, wid = t >> 5;

    // inclusive warp scan
    int v = deg;
#pragma unroll
    for (int o = 1; o < 32; o <<= 1) {
        int n = __shfl_up_sync(0xffffffffu, v, o);
        if (lane >= o) v += n;
    }
    if (lane == 31) wsum[wid] = v;
    __syncthreads();

    if (wid == 0) {
        int w = wsum[lane];
        int wv = w;
#pragma unroll
        for (int o = 1; o < 32; o <<= 1) {
            int n = __shfl_up_sync(0xffffffffu, wv, o);
            if (lane >= o) wv += n;
        }
        wsum[lane] = wv - w;                 // exclusive warp offset
        if (lane == 31)                      // publish block total (+1 = ready)
            *(volatile int*)&g_bflag[b] = wv + 1;
    }
    __syncthreads();

    // lookback: warp 0 sums all earlier block totals (publish precedes wait -> no deadlock)
    if (t < 32) {
        int sum = 0;
        for (int j = t; j < b; j += 32) {
            int vv;
            while ((vv = *(volatile int*)&g_bflag[j]) == 0) { }
            sum += vv - 1;
        }
#pragma unroll
        for (int o = 16; o; o >>= 1) sum += __shfl_down_sync(0xffffffffu, sum, o);
        if (t == 0) s_ex = sum;
    }
    __syncthreads();

    if (i < N_NODES) {
        int incl = v + wsum[wid];
        int rs = s_ex + incl - deg;          // global exclusive prefix
        g_rowstart[i] = rs;
        g_cursor[i] = rs;
        g_dis[i] = rsqrtf((float)(deg + 1)); // +1 self-loop
    }
}

// ---------------- bucket edges into CSR order with precomputed norm ----------------
__global__ void csr_scatter_kernel(const void* ei) {
    int t = blockIdx.x * blockDim.x + threadIdx.x;
    int e = t * 2;
    if (e >= N_EDGES) return;
    int s0, s1, d0, d1;
    if (g_flag32) {
        const int* p = (const int*)ei;
        int2 ss = *(const int2*)(p + e);
        int2 dd = *(const int2*)(p + N_EDGES + e);
        s0 = ss.x; s1 = ss.y; d0 = dd.x; d1 = dd.y;
    } else {
        const long long* p = (const long long*)ei;
        longlong2 ss = *(const longlong2*)(p + e);
        longlong2 dd = *(const longlong2*)(p + N_EDGES + e);
        s0 = (int)ss.x; s1 = (int)ss.y; d0 = (int)dd.x; d1 = (int)dd.y;
    }
    int p0 = atomicAdd(&g_cursor[d0], 1);
    g_edge[p0] = make_float2(__int_as_float(s0), g_dis[s0] * g_dis[d0]);
    int p1 = atomicAdd(&g_cursor[d1], 1);
    g_edge[p1] = make_float2(__int_as_float(s1), g_dis[s1] * g_dis[d1]);
}

// ---------------- GEMM1: h1 = x @ W1 (side stream; 64 rows/block) ----------------
__global__ __launch_bounds__(256) void gemm1_kernel(const float* __restrict__ x,
                                                    const float* __restrict__ W1) {
    __shared__ float xs[64][132];
    __shared__ float ws[48][129];

    int tid = threadIdx.x;
    int row0 = blockIdx.x * 64;

    for (int idx = tid; idx < F0 * F1; idx += 256) {
        int k = idx / F1, c = idx % F1;
        ws[c][k] = W1[idx];
    }
    for (int idx = tid; idx < 64 * F0; idx += 256) {
        int r = idx >> 7, c = idx & 127;
        int row = row0 + r;
        xs[r][c] = (row < N_NODES) ? x[(size_t)row * F0 + c] : 0.0f;
    }
    __syncthreads();

    int tc = tid & 15;
    int tr = tid >> 4;   // 0..15 -> rows tr*4 .. tr*4+3

    float acc[4][3];
#pragma unroll
    for (int i = 0; i < 4; i++)
#pragma unroll
        for (int j = 0; j < 3; j++) acc[i][j] = 0.0f;

#pragma unroll 4
    for (int k = 0; k < F0; k++) {
        float w0 = ws[tc][k];
        float w1 = ws[tc + 16][k];
        float w2 = ws[tc + 32][k];
#pragma unroll
        for (int i = 0; i < 4; i++) {
            float a = xs[tr * 4 + i][k];
            acc[i][0] += a * w0;
            acc[i][1] += a * w1;
            acc[i][2] += a * w2;
        }
    }

#pragma unroll
    for (int i = 0; i < 4; i++) {
        int row = row0 + tr * 4 + i;
        if (row < N_NODES) {
#pragma unroll
            for (int j = 0; j < 3; j++)
                g_h1[(size_t)row * F1 + tc + 16 * j] = acc[i][j];
        }
    }
}

// ---------------- layer-1 gather + bias/relu + block-GEMM2 -> h2 ----------------
#define A1_NODES 128
__global__ __launch_bounds__(256) void agg1_mid_kernel(const float* __restrict__ b1,
                                                       const float* __restrict__ W2) {
    __shared__ __align__(16) float zs[A1_NODES][50];
    __shared__ __align__(16) float ws2t[48][36];       // W2 [k][c], padded

    int tid = threadIdx.x;
    for (int idx = tid; idx < F1 * F2; idx += 256) {
        int k = idx >> 5, c = idx & 31;
        ws2t[k][c] = W2[idx];
    }

    int w = tid >> 5, lane = tid & 31;
    int base = blockIdx.x * A1_NODES;

    float2 b1v = make_float2(0.f, 0.f);
    if (lane < 24) b1v = ((const float2*)b1)[lane];

    // ---- phase 1: gather; 16 nodes per warp, 24 lanes x float2 ----
    for (int i = 0; i < 16; i++) {
        int r = w * 16 + i;
        int node = base + r;
        if (node < N_NODES) {
            if (lane < 24) {
                float ds = g_dis[node];
                float sn = ds * ds;
                float2 hv = ((const float2*)(g_h1 + (size_t)node * F1))[lane];
                float2 acc = make_float2(sn * hv.x, sn * hv.y);

                int rs = g_rowstart[node];
                int re = rs + g_deg[node];
                int e = rs;
                // 8-edge batches (MLP 8)
                for (; e + 8 <= re; e += 8) {
                    float2 ed[8], v[8];
#pragma unroll
                    for (int q = 0; q < 8; q++) ed[q] = g_edge[e + q];
#pragma unroll
                    for (int q = 0; q < 8; q++)
                        v[q] = ((const float2*)(g_h1 + (size_t)__float_as_int(ed[q].x) * F1))[lane];
#pragma unroll
                    for (int q = 0; q < 8; q++) {
                        acc.x += ed[q].y * v[q].x;
                        acc.y += ed[q].y * v[q].y;
                    }
                }
                // 4-edge batch
                if (e + 4 <= re) {
                    float2 ed[4], v[4];
#pragma unroll
                    for (int q = 0; q < 4; q++) ed[q] = g_edge[e + q];
#pragma unroll
                    for (int q = 0; q < 4; q++)
                        v[q] = ((const float2*)(g_h1 + (size_t)__float_as_int(ed[q].x) * F1))[lane];
#pragma unroll
                    for (int q = 0; q < 4; q++) {
                        acc.x += ed[q].y * v[q].x;
                        acc.y += ed[q].y * v[q].y;
                    }
                    e += 4;
                }
                // scalar tail (<=3)
                for (; e < re; e++) {
                    float2 ed = g_edge[e];
                    float2 v = ((const float2*)(g_h1 + (size_t)__float_as_int(ed.x) * F1))[lane];
                    acc.x += ed.y * v.x;
                    acc.y += ed.y * v.y;
                }
                zs[r][2 * lane]     = fmaxf(acc.x + b1v.x, 0.0f);
                zs[r][2 * lane + 1] = fmaxf(acc.y + b1v.y, 0.0f);
            }
        } else if (lane < 24) {
            zs[r][2 * lane] = 0.0f;
            zs[r][2 * lane + 1] = 0.0f;
        }
    }
    __syncthreads();

    // ---- phase 2: h2 = relu(z) @ W2 ; 4 nodes x 4 cols per thread ----
    int ng = tid >> 3;
    int cg = tid & 7;
    int r0 = ng * 4;
    int c0 = cg * 4;

    float acc[4][4];
#pragma unroll
    for (int i = 0; i < 4; i++)
#pragma unroll
        for (int j = 0; j < 4; j++) acc[i][j] = 0.0f;

#pragma unroll 4
    for (int k = 0; k < F1; k++) {
        float4 wv = *(const float4*)&ws2t[k][c0];
        float z0 = zs[r0 + 0][k];
        float z1 = zs[r0 + 1][k];
        float z2 = zs[r0 + 2][k];
        float z3 = zs[r0 + 3][k];
        acc[0][0] += z0 * wv.x; acc[0][1] += z0 * wv.y; acc[0][2] += z0 * wv.z; acc[0][3] += z0 * wv.w;
        acc[1][0] += z1 * wv.x; acc[1][1] += z1 * wv.y; acc[1][2] += z1 * wv.z; acc[1][3] += z1 * wv.w;
        acc[2][0] += z2 * wv.x; acc[2][1] += z2 * wv.y; acc[2][2] += z2 * wv.z; acc[2][3] += z2 * wv.w;
        acc[3][0] += z3 * wv.x; acc[3][1] += z3 * wv.y; acc[3][2] += z3 * wv.z; acc[3][3] += z3 * wv.w;
    }

#pragma unroll
    for (int i = 0; i < 4; i++) {
        int node = base + r0 + i;
        if (node < N_NODES)
            *(float4*)(g_h2 + (size_t)node * F2 + c0) =
                make_float4(acc[i][0], acc[i][1], acc[i][2], acc[i][3]);
    }
}

// ---------------- layer-2 gather + bias -> out (persistent grid-stride) ----------------
#define A2_BLOCKS 592
__global__ __launch_bounds__(512) void agg2_kernel(const float* __restrict__ b2,
                                                   float* __restrict__ out) {
    int tid = threadIdx.x;
    int w = tid >> 5, lane = tid & 31;
    int warp_g = blockIdx.x * 16 + w;
    int n_warps = gridDim.x * 16;
    float bias = b2[lane];

    for (int row = warp_g; row < N_NODES; row += n_warps) {
        float ds = g_dis[row];
        float acc = ds * ds * g_h2[(size_t)row * F2 + lane];

        int rs = g_rowstart[row];
        int re = rs + g_deg[row];
        int e = rs;
        for (; e + 8 <= re; e += 8) {
            float2 ed[8]; float v[8];
#pragma unroll
            for (int q = 0; q < 8; q++) ed[q] = g_edge[e + q];
#pragma unroll
            for (int q = 0; q < 8; q++)
                v[q] = __ldg(g_h2 + (size_t)__float_as_int(ed[q].x) * F2 + lane);
#pragma unroll
            for (int q = 0; q < 8; q++) acc += ed[q].y * v[q];
        }
        if (e + 4 <= re) {
            float2 ed[4]; float v[4];
#pragma unroll
            for (int q = 0; q < 4; q++) ed[q] = g_edge[e + q];
#pragma unroll
            for (int q = 0; q < 4; q++)
                v[q] = __ldg(g_h2 + (size_t)__float_as_int(ed[q].x) * F2 + lane);
#pragma unroll
            for (int q = 0; q < 4; q++) acc += ed[q].y * v[q];
            e += 4;
        }
        for (; e < re; e++) {
            float2 ed = g_edge[e];
            acc += ed.y * __ldg(g_h2 + (size_t)__float_as_int(ed.x) * F2 + lane);
        }
        out[(size_t)row * F2 + lane] = acc + bias;
    }
}

// ---------------- launch: fork gemm1 onto a side stream to overlap CSR build ----------------
extern "C" void kernel_launch(void* const* d_in, const int* in_sizes, int n_in,
                              void* d_out, int out_size) {
    const float* x  = (const float*)d_in[0];
    const void*  ei = d_in[1];
    const float* W1 = (const float*)d_in[2];
    const float* b1 = (const float*)d_in[3];
    const float* W2 = (const float*)d_in[4];
    const float* b2 = (const float*)d_in[5];
    float* out = (float*)d_out;

    cudaStream_t s2;
    cudaStreamCreateWithFlags(&s2, cudaStreamNonBlocking);
    cudaEvent_t evRoot, evG;
    cudaEventCreateWithFlags(&evRoot, cudaEventDisableTiming);
    cudaEventCreateWithFlags(&evG, cudaEventDisableTiming);

    // fork: gemm1 depends only on x/W1
    cudaEventRecord(evRoot, 0);
    cudaStreamWaitEvent(s2, evRoot, 0);
    gemm1_kernel<<<(N_NODES + 63) / 64, 256, 0, s2>>>(x, W1);
    cudaEventRecord(evG, s2);

    // main chain: CSR build
    init_kernel<<<(N_NODES + 255) / 256, 256>>>(ei);
    count_kernel<<<(N_EDGES / 2 + 255) / 256, 256>>>(ei);
    scan_kernel<<<N_SCAN_BLK, SCAN_B>>>();
    csr_scatter_kernel<<<(N_EDGES / 2 + 255) / 256, 256>>>(ei);

    // join, then the two gather stages
    cudaStreamWaitEvent(0, evG, 0);
    agg1_mid_kernel<<<(N_NODES + A1_NODES - 1) / A1_NODES, 256>>>(b1, W2);
    agg2_kernel<<<A2_BLOCKS, 512>>>(b2, out);
}

// round 5
// speedup vs baseline: 2.5476x; 1.2202x over previous
#include <cuda_runtime.h>
#include <cuda_fp16.h>
#include <cstdint>

#define N_NODES 100000
#define N_EDGES 1600000
#define F0 128
#define F1 48
#define F2 32
#define SCAN_B 1024
#define SCAN_ITEMS 4
#define SCAN_TILE (SCAN_B * SCAN_ITEMS)
#define N_SCAN_BLK ((N_NODES + SCAN_TILE - 1) / SCAN_TILE)   // 25

// ---------------- scratch (static device globals; no allocation) ----------------
__device__ int    g_flag32;
__device__ __align__(16) int    g_deg[N_NODES];
__device__ int    g_bflag[N_SCAN_BLK];     // lookback: 0 = not ready, else blocksum+1
__device__ __align__(16) int    g_rowstart[N_NODES];
__device__ __align__(16) int    g_cursor[N_NODES];
__device__ __align__(16) float  g_dis[N_NODES];
__device__ __align__(16) int    g_esrc[N_EDGES];                   // CSR-ordered src
__device__ __align__(16) __half g_h1h[(size_t)N_NODES * F1];       // dis * (x@W1), fp16
__device__ __align__(16) __half g_h2h[(size_t)N_NODES * F2];       // dis * h2, fp16

// ---------------- init: zero deg + flags, dtype detect ----------------
__global__ void init_kernel(const void* ei) {
    int i = blockIdx.x * blockDim.x + threadIdx.x;
    if (i < N_NODES) g_deg[i] = 0;
    if (i < N_SCAN_BLK) g_bflag[i] = 0;
    if (i == 0) {
        const long long* p = (const long long*)ei;
        int is32 = 0;
        for (int k = 0; k < 256; k++) {
            unsigned long long v = (unsigned long long)p[k];
            if (v >= (unsigned long long)N_NODES) { is32 = 1; break; }
        }
        g_flag32 = is32;
    }
}

// ---------------- degree histogram: 4 edges/thread ----------------
__global__ void count_kernel(const void* ei) {
    int t = blockIdx.x * blockDim.x + threadIdx.x;
    int e = t * 4;
    if (e >= N_EDGES) return;
    int d0, d1, d2, d3;
    if (g_flag32) {
        int4 dd = *(const int4*)((const int*)ei + N_EDGES + e);
        d0 = dd.x; d1 = dd.y; d2 = dd.z; d3 = dd.w;
    } else {
        const long long* p = (const long long*)ei + N_EDGES + e;
        longlong2 a = *(const longlong2*)p;
        longlong2 b = *(const longlong2*)(p + 2);
        d0 = (int)a.x; d1 = (int)a.y; d2 = (int)b.x; d3 = (int)b.y;
    }
    atomicAdd(&g_deg[d0], 1);
    atomicAdd(&g_deg[d1], 1);
    atomicAdd(&g_deg[d2], 1);
    atomicAdd(&g_deg[d3], 1);
}

// ---------------- fused scan (4 items/thread): rowstart/cursor/dis ----------------
__global__ __launch_bounds__(SCAN_B) void scan_kernel() {
    __shared__ int wsum[32];
    __shared__ int s_ex;
    int t = threadIdx.x, b = blockIdx.x;
    int i0 = (b * SCAN_B + t) * SCAN_ITEMS;
    int lane = t & 31, wid = t >> 5;

    int4 d4 = make_int4(0, 0, 0, 0);
    if (i0 < N_NODES) d4 = *(const int4*)&g_deg[i0];   // N_NODES % 4 == 0
    int mysum = d4.x + d4.y + d4.z + d4.w;

    // inclusive warp scan of per-thread sums
    int v = mysum;
#pragma unroll
    for (int o = 1; o < 32; o <<= 1) {
        int n = __shfl_up_sync(0xffffffffu, v, o);
        if (lane >= o) v += n;
    }
    if (lane == 31) wsum[wid] = v;
    __syncthreads();

    if (wid == 0) {
        int w = wsum[lane];
        int wv = w;
#pragma unroll
        for (int o = 1; o < 32; o <<= 1) {
            int n = __shfl_up_sync(0xffffffffu, wv, o);
            if (lane >= o) wv += n;
        }
        wsum[lane] = wv - w;                 // exclusive warp offset
        if (lane == 31)
            *(volatile int*)&g_bflag[b] = wv + 1;   // publish block total (+1 = ready)
    }
    __syncthreads();

    // lookback: warp 0 sums earlier block totals (publish precedes wait -> no deadlock)
    if (t < 32) {
        int sum = 0;
        for (int j = t; j < b; j += 32) {
            int vv;
            while ((vv = *(volatile int*)&g_bflag[j]) == 0) { }
            sum += vv - 1;
        }
#pragma unroll
        for (int o = 16; o; o >>= 1) sum += __shfl_down_sync(0xffffffffu, sum, o);
        if (t == 0) s_ex = sum;
    }
    __syncthreads();

    if (i0 < N_NODES) {
        int ex = s_ex + wsum[wid] + (v - mysum);   // exclusive prefix at i0
        int4 rs;
        rs.x = ex;
        rs.y = ex + d4.x;
        rs.z = rs.y + d4.y;
        rs.w = rs.z + d4.z;
        *(int4*)&g_rowstart[i0] = rs;
        *(int4*)&g_cursor[i0] = rs;
        float4 dis;
        dis.x = rsqrtf((float)(d4.x + 1));
        dis.y = rsqrtf((float)(d4.y + 1));
        dis.z = rsqrtf((float)(d4.z + 1));
        dis.w = rsqrtf((float)(d4.w + 1));
        *(float4*)&g_dis[i0] = dis;
    }
}

// ---------------- bucket edges into CSR order (src only, 4B records) ----------------
__global__ void csr_scatter_kernel(const void* ei) {
    int t = blockIdx.x * blockDim.x + threadIdx.x;
    int e = t * 2;
    if (e >= N_EDGES) return;
    int s0, s1, d0, d1;
    if (g_flag32) {
        const int* p = (const int*)ei;
        int2 ss = *(const int2*)(p + e);
        int2 dd = *(const int2*)(p + N_EDGES + e);
        s0 = ss.x; s1 = ss.y; d0 = dd.x; d1 = dd.y;
    } else {
        const long long* p = (const long long*)ei;
        longlong2 ss = *(const longlong2*)(p + e);
        longlong2 dd = *(const longlong2*)(p + N_EDGES + e);
        s0 = (int)ss.x; s1 = (int)ss.y; d0 = (int)dd.x; d1 = (int)dd.y;
    }
    g_esrc[atomicAdd(&g_cursor[d0], 1)] = s0;
    g_esrc[atomicAdd(&g_cursor[d1], 1)] = s1;
}

// ---------------- GEMM1: h1s = dis * (x @ W1) -> fp16 (side stream, after scan) ----------------
__global__ __launch_bounds__(256) void gemm1_kernel(const float* __restrict__ x,
                                                    const float* __restrict__ W1) {
    __shared__ float xs[64][132];
    __shared__ float ws[48][129];

    int tid = threadIdx.x;
    int row0 = blockIdx.x * 64;

    for (int idx = tid; idx < F0 * F1; idx += 256) {
        int k = idx / F1, c = idx % F1;
        ws[c][k] = W1[idx];
    }
    for (int idx = tid; idx < 64 * F0; idx += 256) {
        int r = idx >> 7, c = idx & 127;
        int row = row0 + r;
        xs[r][c] = (row < N_NODES) ? x[(size_t)row * F0 + c] : 0.0f;
    }
    __syncthreads();

    int tc = tid & 15;
    int tr = tid >> 4;

    float acc[4][3];
#pragma unroll
    for (int i = 0; i < 4; i++)
#pragma unroll
        for (int j = 0; j < 3; j++) acc[i][j] = 0.0f;

#pragma unroll 4
    for (int k = 0; k < F0; k++) {
        float w0 = ws[tc][k];
        float w1 = ws[tc + 16][k];
        float w2 = ws[tc + 32][k];
#pragma unroll
        for (int i = 0; i < 4; i++) {
            float a = xs[tr * 4 + i][k];
            acc[i][0] += a * w0;
            acc[i][1] += a * w1;
            acc[i][2] += a * w2;
        }
    }

#pragma unroll
    for (int i = 0; i < 4; i++) {
        int row = row0 + tr * 4 + i;
        if (row < N_NODES) {
            float d = g_dis[row];
#pragma unroll
            for (int j = 0; j < 3; j++)
                g_h1h[(size_t)row * F1 + tc + 16 * j] = __float2half_rn(acc[i][j] * d);
        }
    }
}

// ---------------- layer-1 gather + bias/relu + block-GEMM2 -> h2s (fp16) ----------------
#define A1_NODES 128
__global__ __launch_bounds__(256) void agg1_mid_kernel(const float* __restrict__ b1,
                                                       const float* __restrict__ W2) {
    __shared__ __align__(16) float zs[A1_NODES][50];
    __shared__ __align__(16) float ws2t[48][36];       // W2 [k][c], padded

    int tid = threadIdx.x;
    for (int idx = tid; idx < F1 * F2; idx += 256) {
        int k = idx >> 5, c = idx & 31;
        ws2t[k][c] = W2[idx];
    }

    int w = tid >> 5, lane = tid & 31;
    int base = blockIdx.x * A1_NODES;

    float2 b1v = make_float2(0.f, 0.f);
    if (lane < 24) b1v = ((const float2*)b1)[lane];

    // ---- phase 1: gather; 16 nodes per warp, 24 lanes x half2 ----
    for (int i = 0; i < 16; i++) {
        int r = w * 16 + i;
        int node = base + r;
        if (node < N_NODES) {
            if (lane < 24) {
                float drow = g_dis[node];
                // self term: dis^2*h1 = dis*h1s ; total acc gets *dis at end
                float2 acc = __half22float2(((const __half2*)(g_h1h + (size_t)node * F1))[lane]);

                int rs = g_rowstart[node];
                int re = rs + g_deg[node];
                int e = rs;
                for (; e + 8 <= re; e += 8) {
                    int s[8]; float2 v[8];
#pragma unroll
                    for (int q = 0; q < 8; q++) s[q] = g_esrc[e + q];
#pragma unroll
                    for (int q = 0; q < 8; q++)
                        v[q] = __half22float2(((const __half2*)(g_h1h + (size_t)s[q] * F1))[lane]);
#pragma unroll
                    for (int q = 0; q < 8; q++) { acc.x += v[q].x; acc.y += v[q].y; }
                }
                if (e + 4 <= re) {
                    int s[4]; float2 v[4];
#pragma unroll
                    for (int q = 0; q < 4; q++) s[q] = g_esrc[e + q];
#pragma unroll
                    for (int q = 0; q < 4; q++)
                        v[q] = __half22float2(((const __half2*)(g_h1h + (size_t)s[q] * F1))[lane]);
#pragma unroll
                    for (int q = 0; q < 4; q++) { acc.x += v[q].x; acc.y += v[q].y; }
                    e += 4;
                }
                for (; e < re; e++) {
                    float2 v = __half22float2(((const __half2*)(g_h1h + (size_t)g_esrc[e] * F1))[lane]);
                    acc.x += v.x; acc.y += v.y;
                }
                zs[r][2 * lane]     = fmaxf(fmaf(drow, acc.x, b1v.x), 0.0f);
                zs[r][2 * lane + 1] = fmaxf(fmaf(drow, acc.y, b1v.y), 0.0f);
            }
        } else if (lane < 24) {
            zs[r][2 * lane] = 0.0f;
            zs[r][2 * lane + 1] = 0.0f;
        }
    }
    __syncthreads();

    // ---- phase 2: h2s = dis * (relu(z) @ W2) -> fp16 ; 4 nodes x 4 cols per thread ----
    int ng = tid >> 3;
    int cg = tid & 7;
    int r0 = ng * 4;
    int c0 = cg * 4;

    float acc[4][4];
#pragma unroll
    for (int i = 0; i < 4; i++)
#pragma unroll
        for (int j = 0; j < 4; j++) acc[i][j] = 0.0f;

#pragma unroll 4
    for (int k = 0; k < F1; k++) {
        float4 wv = *(const float4*)&ws2t[k][c0];
        float z0 = zs[r0 + 0][k];
        float z1 = zs[r0 + 1][k];
        float z2 = zs[r0 + 2][k];
        float z3 = zs[r0 + 3][k];
        acc[0][0] += z0 * wv.x; acc[0][1] += z0 * wv.y; acc[0][2] += z0 * wv.z; acc[0][3] += z0 * wv.w;
        acc[1][0] += z1 * wv.x; acc[1][1] += z1 * wv.y; acc[1][2] += z1 * wv.z; acc[1][3] += z1 * wv.w;
        acc[2][0] += z2 * wv.x; acc[2][1] += z2 * wv.y; acc[2][2] += z2 * wv.z; acc[2][3] += z2 * wv.w;
        acc[3][0] += z3 * wv.x; acc[3][1] += z3 * wv.y; acc[3][2] += z3 * wv.z; acc[3][3] += z3 * wv.w;
    }

#pragma unroll
    for (int i = 0; i < 4; i++) {
        int node = base + r0 + i;
        if (node < N_NODES) {
            float d = g_dis[node];
            __half2 p0 = __floats2half2_rn(acc[i][0] * d, acc[i][1] * d);
            __half2 p1 = __floats2half2_rn(acc[i][2] * d, acc[i][3] * d);
            uint2 pk;
            pk.x = *(unsigned*)&p0;
            pk.y = *(unsigned*)&p1;
            *(uint2*)(g_h2h + (size_t)node * F2 + c0) = pk;
        }
    }
}

// ---------------- layer-2 gather + bias -> out (persistent grid-stride) ----------------
#define A2_BLOCKS 592
__global__ __launch_bounds__(512) void agg2_kernel(const float* __restrict__ b2,
                                                   float* __restrict__ out) {
    int tid = threadIdx.x;
    int w = tid >> 5, lane = tid & 31;
    int warp_g = blockIdx.x * 16 + w;
    int n_warps = gridDim.x * 16;
    float bias = b2[lane];

    for (int row = warp_g; row < N_NODES; row += n_warps) {
        float drow = g_dis[row];
        // self: dis^2*h2 = dis*h2s ; whole acc *dis at end
        float acc = __half2float(g_h2h[(size_t)row * F2 + lane]);

        int rs = g_rowstart[row];
        int re = rs + g_deg[row];
        int e = rs;
        for (; e + 8 <= re; e += 8) {
            int s[8]; float v[8];
#pragma unroll
            for (int q = 0; q < 8; q++) s[q] = g_esrc[e + q];
#pragma unroll
            for (int q = 0; q < 8; q++)
                v[q] = __half2float(__ldg(g_h2h + (size_t)s[q] * F2 + lane));
#pragma unroll
            for (int q = 0; q < 8; q++) acc += v[q];
        }
        if (e + 4 <= re) {
            int s[4]; float v[4];
#pragma unroll
            for (int q = 0; q < 4; q++) s[q] = g_esrc[e + q];
#pragma unroll
            for (int q = 0; q < 4; q++)
                v[q] = __half2float(__ldg(g_h2h + (size_t)s[q] * F2 + lane));
#pragma unroll
            for (int q = 0; q < 4; q++) acc += v[q];
            e += 4;
        }
        for (; e < re; e++)
            acc += __half2float(__ldg(g_h2h + (size_t)g_esrc[e] * F2 + lane));

        out[(size_t)row * F2 + lane] = fmaf(drow, acc, bias);
    }
}

// ---------------- launch ----------------
extern "C" void kernel_launch(void* const* d_in, const int* in_sizes, int n_in,
                              void* d_out, int out_size) {
    const float* x  = (const float*)d_in[0];
    const void*  ei = d_in[1];
    const float* W1 = (const float*)d_in[2];
    const float* b1 = (const float*)d_in[3];
    const float* W2 = (const float*)d_in[4];
    const float* b2 = (const float*)d_in[5];
    float* out = (float*)d_out;

    cudaStream_t s2;
    cudaStreamCreateWithFlags(&s2, cudaStreamNonBlocking);
    cudaEvent_t evScan, evG;
    cudaEventCreateWithFlags(&evScan, cudaEventDisableTiming);
    cudaEventCreateWithFlags(&evG, cudaEventDisableTiming);

    // main chain: CSR build (dis ready after scan)
    init_kernel<<<(N_NODES + 255) / 256, 256>>>(ei);
    count_kernel<<<(N_EDGES / 4 + 255) / 256, 256>>>(ei);
    scan_kernel<<<N_SCAN_BLK, SCAN_B>>>();
    cudaEventRecord(evScan, 0);

    // side stream: gemm1 (needs dis) overlaps csr_scatter
    cudaStreamWaitEvent(s2, evScan, 0);
    gemm1_kernel<<<(N_NODES + 63) / 64, 256, 0, s2>>>(x, W1);
    cudaEventRecord(evG, s2);

    csr_scatter_kernel<<<(N_EDGES / 2 + 255) / 256, 256>>>(ei);

    // join, then the two gather stages
    cudaStreamWaitEvent(0, evG, 0);
    agg1_mid_kernel<<<(N_NODES + A1_NODES - 1) / A1_NODES, 256>>>(b1, W2);
    agg2_kernel<<<A2_BLOCKS, 512>>>(b2, out);
}

// round 6
// speedup vs baseline: 2.6491x; 1.0399x over previous
#include <cuda_runtime.h>
#include <cuda_fp16.h>
#include <cstdint>

#define N_NODES 100000
#define N_EDGES 1600000
#define F0 128
#define F1 48
#define F2 32
#define SCAN_B 1024
#define SCAN_ITEMS 4
#define SCAN_TILE (SCAN_B * SCAN_ITEMS)
#define N_SCAN_BLK ((N_NODES + SCAN_TILE - 1) / SCAN_TILE)   // 25

typedef unsigned long long u64;

// packed fp32x2 FMA (Blackwell FFMA2)
#define FMA_F32X2(d, a, b, c) \
    asm("fma.rn.f32x2 %0, %1, %2, %3;" : "=l"(d) : "l"(a), "l"(b), "l"(c))

// ---------------- scratch (static device globals; no allocation) ----------------
__device__ int    g_flag32;
__device__ __align__(16) int    g_deg[N_NODES];
__device__ int    g_bflag[N_SCAN_BLK];
__device__ __align__(16) int    g_rowstart[N_NODES];
__device__ __align__(16) int    g_cursor[N_NODES];
__device__ __align__(16) float  g_dis[N_NODES];
__device__ __align__(16) int    g_esrc[N_EDGES];                   // CSR-ordered src
__device__ __align__(16) __half g_h1h[(size_t)N_NODES * F1];       // dis * (x@W1), fp16
__device__ __align__(16) __half g_h2h[(size_t)N_NODES * F2];       // dis * h2, fp16

__device__ __forceinline__ float4 h4_to_f4(uint2 u) {
    float2 a = __half22float2(*(__half2*)&u.x);
    float2 b = __half22float2(*(__half2*)&u.y);
    return make_float4(a.x, a.y, b.x, b.y);
}

// ---------------- init: zero deg + flags, dtype detect ----------------
__global__ void init_kernel(const void* ei) {
    int i = blockIdx.x * blockDim.x + threadIdx.x;
    if (i < N_NODES) g_deg[i] = 0;
    if (i < N_SCAN_BLK) g_bflag[i] = 0;
    if (i == 0) {
        const long long* p = (const long long*)ei;
        int is32 = 0;
        for (int k = 0; k < 256; k++) {
            unsigned long long v = (unsigned long long)p[k];
            if (v >= (unsigned long long)N_NODES) { is32 = 1; break; }
        }
        g_flag32 = is32;
    }
}

// ---------------- degree histogram: 4 edges/thread ----------------
__global__ void count_kernel(const void* ei) {
    int t = blockIdx.x * blockDim.x + threadIdx.x;
    int e = t * 4;
    if (e >= N_EDGES) return;
    int d0, d1, d2, d3;
    if (g_flag32) {
        int4 dd = *(const int4*)((const int*)ei + N_EDGES + e);
        d0 = dd.x; d1 = dd.y; d2 = dd.z; d3 = dd.w;
    } else {
        const long long* p = (const long long*)ei + N_EDGES + e;
        longlong2 a = *(const longlong2*)p;
        longlong2 b = *(const longlong2*)(p + 2);
        d0 = (int)a.x; d1 = (int)a.y; d2 = (int)b.x; d3 = (int)b.y;
    }
    atomicAdd(&g_deg[d0], 1);
    atomicAdd(&g_deg[d1], 1);
    atomicAdd(&g_deg[d2], 1);
    atomicAdd(&g_deg[d3], 1);
}

// ---------------- fused scan (4 items/thread): rowstart/cursor/dis ----------------
__global__ __launch_bounds__(SCAN_B) void scan_kernel() {
    __shared__ int wsum[32];
    __shared__ int s_ex;
    int t = threadIdx.x, b = blockIdx.x;
    int i0 = (b * SCAN_B + t) * SCAN_ITEMS;
    int lane = t & 31, wid = t >> 5;

    int4 d4 = make_int4(0, 0, 0, 0);
    if (i0 < N_NODES) d4 = *(const int4*)&g_deg[i0];   // N_NODES % 4 == 0
    int mysum = d4.x + d4.y + d4.z + d4.w;

    int v = mysum;
#pragma unroll
    for (int o = 1; o < 32; o <<= 1) {
        int n = __shfl_up_sync(0xffffffffu, v, o);
        if (lane >= o) v += n;
    }
    if (lane == 31) wsum[wid] = v;
    __syncthreads();

    if (wid == 0) {
        int w = wsum[lane];
        int wv = w;
#pragma unroll
        for (int o = 1; o < 32; o <<= 1) {
            int n = __shfl_up_sync(0xffffffffu, wv, o);
            if (lane >= o) wv += n;
        }
        wsum[lane] = wv - w;
        if (lane == 31)
            *(volatile int*)&g_bflag[b] = wv + 1;
    }
    __syncthreads();

    if (t < 32) {
        int sum = 0;
        for (int j = t; j < b; j += 32) {
            int vv;
            while ((vv = *(volatile int*)&g_bflag[j]) == 0) { }
            sum += vv - 1;
        }
#pragma unroll
        for (int o = 16; o; o >>= 1) sum += __shfl_down_sync(0xffffffffu, sum, o);
        if (t == 0) s_ex = sum;
    }
    __syncthreads();

    if (i0 < N_NODES) {
        int ex = s_ex + wsum[wid] + (v - mysum);
        int4 rs;
        rs.x = ex;
        rs.y = ex + d4.x;
        rs.z = rs.y + d4.y;
        rs.w = rs.z + d4.z;
        *(int4*)&g_rowstart[i0] = rs;
        *(int4*)&g_cursor[i0] = rs;
        float4 dis;
        dis.x = rsqrtf((float)(d4.x + 1));
        dis.y = rsqrtf((float)(d4.y + 1));
        dis.z = rsqrtf((float)(d4.z + 1));
        dis.w = rsqrtf((float)(d4.w + 1));
        *(float4*)&g_dis[i0] = dis;
    }
}

// ---------------- bucket edges into CSR order (src only, 4B records) ----------------
__global__ void csr_scatter_kernel(const void* ei) {
    int t = blockIdx.x * blockDim.x + threadIdx.x;
    int e = t * 2;
    if (e >= N_EDGES) return;
    int s0, s1, d0, d1;
    if (g_flag32) {
        const int* p = (const int*)ei;
        int2 ss = *(const int2*)(p + e);
        int2 dd = *(const int2*)(p + N_EDGES + e);
        s0 = ss.x; s1 = ss.y; d0 = dd.x; d1 = dd.y;
    } else {
        const long long* p = (const long long*)ei;
        longlong2 ss = *(const longlong2*)(p + e);
        longlong2 dd = *(const longlong2*)(p + N_EDGES + e);
        s0 = (int)ss.x; s1 = (int)ss.y; d0 = (int)dd.x; d1 = (int)dd.y;
    }
    g_esrc[atomicAdd(&g_cursor[d0], 1)] = s0;
    g_esrc[atomicAdd(&g_cursor[d1], 1)] = s1;
}

// ---------------- GEMM1: h1s = dis * (x @ W1) -> fp16, packed f32x2 FMA ----------------
__global__ __launch_bounds__(256) void gemm1_kernel(const float* __restrict__ x,
                                                    const float* __restrict__ W1) {
    __shared__ float xs[64][132];   // even stride: 8B-aligned k-pairs
    __shared__ float ws[48][130];   // even stride

    int tid = threadIdx.x;
    int row0 = blockIdx.x * 64;

    for (int idx = tid; idx < F0 * F1; idx += 256) {
        int k = idx / F1, c = idx % F1;
        ws[c][k] = W1[idx];
    }
    for (int idx = tid; idx < 64 * F0; idx += 256) {
        int r = idx >> 7, c = idx & 127;
        int row = row0 + r;
        xs[r][c] = (row < N_NODES) ? x[(size_t)row * F0 + c] : 0.0f;
    }
    __syncthreads();

    int tc = tid & 15;
    int tr = tid >> 4;

    u64 acc2[4][3];
#pragma unroll
    for (int i = 0; i < 4; i++)
#pragma unroll
        for (int j = 0; j < 3; j++) acc2[i][j] = 0ull;   // packed (+0.0f, +0.0f)

#pragma unroll 4
    for (int k = 0; k < F0; k += 2) {
        u64 w0 = *(const u64*)&ws[tc][k];
        u64 w1 = *(const u64*)&ws[tc + 16][k];
        u64 w2 = *(const u64*)&ws[tc + 32][k];
#pragma unroll
        for (int i = 0; i < 4; i++) {
            u64 a = *(const u64*)&xs[tr * 4 + i][k];
            FMA_F32X2(acc2[i][0], a, w0, acc2[i][0]);
            FMA_F32X2(acc2[i][1], a, w1, acc2[i][1]);
            FMA_F32X2(acc2[i][2], a, w2, acc2[i][2]);
        }
    }

#pragma unroll
    for (int i = 0; i < 4; i++) {
        int row = row0 + tr * 4 + i;
        if (row < N_NODES) {
            float d = g_dis[row];
#pragma unroll
            for (int j = 0; j < 3; j++) {
                float lo, hi;
                asm("mov.b64 {%0, %1}, %2;" : "=f"(lo), "=f"(hi) : "l"(acc2[i][j]));
                g_h1h[(size_t)row * F1 + tc + 16 * j] = __float2half_rn((lo + hi) * d);
            }
        }
    }
}

// ---------------- layer-1 gather + bias/relu + block-GEMM2 -> h2s (fp16) ----------------
// phase 1: 12 lanes per node (uint2 = 4 halves/lane), 2 nodes per warp concurrently.
#define A1_NODES 128
__global__ __launch_bounds__(256) void agg1_mid_kernel(const float* __restrict__ b1,
                                                       const float* __restrict__ W2) {
    __shared__ __align__(16) float zs[A1_NODES][52];   // stride 52 floats = 208B (16B mult)
    __shared__ __align__(16) float ws2t[48][36];       // W2 [k][c], padded

    int tid = threadIdx.x;
    for (int idx = tid; idx < F1 * F2; idx += 256) {
        int k = idx >> 5, c = idx & 31;
        ws2t[k][c] = W2[idx];
    }

    int w = tid >> 5, lane = tid & 31;
    int base = blockIdx.x * A1_NODES;
    bool active = lane < 24;
    int grp = lane / 12;      // 0 or 1 (active lanes)
    int sl  = lane % 12;      // sub-lane: 4 halves each

    float4 b1v = make_float4(0.f, 0.f, 0.f, 0.f);
    if (active) b1v = ((const float4*)b1)[sl];

    // ---- phase 1: 8 iterations x 2 nodes per warp ----
    for (int i = 0; i < 8; i++) {
        int r = w * 16 + i * 2 + grp;
        int node = base + r;
        if (active) {
            if (node < N_NODES) {
                float drow = g_dis[node];
                const __half* hrow = g_h1h + (size_t)node * F1 + sl * 4;
                float4 acc = h4_to_f4(*(const uint2*)hrow);   // self: dis*h1s

                int rs = g_rowstart[node];
                int re = rs + g_deg[node];
                int e = rs;
                for (; e + 8 <= re; e += 8) {
                    int s[8]; uint2 u[8];
#pragma unroll
                    for (int q = 0; q < 8; q++) s[q] = g_esrc[e + q];
#pragma unroll
                    for (int q = 0; q < 8; q++)
                        u[q] = *(const uint2*)(g_h1h + (size_t)s[q] * F1 + sl * 4);
#pragma unroll
                    for (int q = 0; q < 8; q++) {
                        float4 v = h4_to_f4(u[q]);
                        acc.x += v.x; acc.y += v.y; acc.z += v.z; acc.w += v.w;
                    }
                }
                if (e + 4 <= re) {
                    int s[4]; uint2 u[4];
#pragma unroll
                    for (int q = 0; q < 4; q++) s[q] = g_esrc[e + q];
#pragma unroll
                    for (int q = 0; q < 4; q++)
                        u[q] = *(const uint2*)(g_h1h + (size_t)s[q] * F1 + sl * 4);
#pragma unroll
                    for (int q = 0; q < 4; q++) {
                        float4 v = h4_to_f4(u[q]);
                        acc.x += v.x; acc.y += v.y; acc.z += v.z; acc.w += v.w;
                    }
                    e += 4;
                }
                for (; e < re; e++) {
                    float4 v = h4_to_f4(*(const uint2*)(g_h1h + (size_t)g_esrc[e] * F1 + sl * 4));
                    acc.x += v.x; acc.y += v.y; acc.z += v.z; acc.w += v.w;
                }
                float4 z;
                z.x = fmaxf(fmaf(drow, acc.x, b1v.x), 0.0f);
                z.y = fmaxf(fmaf(drow, acc.y, b1v.y), 0.0f);
                z.z = fmaxf(fmaf(drow, acc.z, b1v.z), 0.0f);
                z.w = fmaxf(fmaf(drow, acc.w, b1v.w), 0.0f);
                *(float4*)&zs[r][sl * 4] = z;
            } else {
                *(float4*)&zs[r][sl * 4] = make_float4(0.f, 0.f, 0.f, 0.f);
            }
        }
    }
    __syncthreads();

    // ---- phase 2: h2s = dis * (relu(z) @ W2) -> fp16 ; 4 nodes x 4 cols per thread ----
    int ng = tid >> 3;
    int cg = tid & 7;
    int r0 = ng * 4;
    int c0 = cg * 4;

    float acc[4][4];
#pragma unroll
    for (int i = 0; i < 4; i++)
#pragma unroll
        for (int j = 0; j < 4; j++) acc[i][j] = 0.0f;

#pragma unroll 4
    for (int k = 0; k < F1; k++) {
        float4 wv = *(const float4*)&ws2t[k][c0];
        float z0 = zs[r0 + 0][k];
        float z1 = zs[r0 + 1][k];
        float z2 = zs[r0 + 2][k];
        float z3 = zs[r0 + 3][k];
        acc[0][0] += z0 * wv.x; acc[0][1] += z0 * wv.y; acc[0][2] += z0 * wv.z; acc[0][3] += z0 * wv.w;
        acc[1][0] += z1 * wv.x; acc[1][1] += z1 * wv.y; acc[1][2] += z1 * wv.z; acc[1][3] += z1 * wv.w;
        acc[2][0] += z2 * wv.x; acc[2][1] += z2 * wv.y; acc[2][2] += z2 * wv.z; acc[2][3] += z2 * wv.w;
        acc[3][0] += z3 * wv.x; acc[3][1] += z3 * wv.y; acc[3][2] += z3 * wv.z; acc[3][3] += z3 * wv.w;
    }

#pragma unroll
    for (int i = 0; i < 4; i++) {
        int node = base + r0 + i;
        if (node < N_NODES) {
            float d = g_dis[node];
            __half2 p0 = __floats2half2_rn(acc[i][0] * d, acc[i][1] * d);
            __half2 p1 = __floats2half2_rn(acc[i][2] * d, acc[i][3] * d);
            uint2 pk;
            pk.x = *(unsigned*)&p0;
            pk.y = *(unsigned*)&p1;
            *(uint2*)(g_h2h + (size_t)node * F2 + c0) = pk;
        }
    }
}

// ---------------- layer-2 gather + bias -> out ----------------
// 16 lanes per node (half2/lane), 2 nodes per warp; persistent grid-stride.
#define A2_BLOCKS 592
__global__ __launch_bounds__(512) void agg2_kernel(const float* __restrict__ b2,
                                                   float* __restrict__ out) {
    int tid = threadIdx.x;
    int w = tid >> 5, lane = tid & 31;
    int grp = lane >> 4, sl = lane & 15;
    int pair0 = blockIdx.x * 16 + w;       // warp's node-pair index
    int n_pairs = gridDim.x * 16;
    float2 b2v = ((const float2*)b2)[sl];

    for (int p = pair0; p * 2 + grp < N_NODES; p += n_pairs) {
        int row = p * 2 + grp;
        float drow = g_dis[row];
        float2 acc = __half22float2(((const __half2*)(g_h2h + (size_t)row * F2))[sl]);

        int rs = g_rowstart[row];
        int re = rs + g_deg[row];
        int e = rs;
        for (; e + 8 <= re; e += 8) {
            int s[8]; __half2 v[8];
#pragma unroll
            for (int q = 0; q < 8; q++) s[q] = g_esrc[e + q];
#pragma unroll
            for (int q = 0; q < 8; q++)
                v[q] = ((const __half2*)(g_h2h + (size_t)s[q] * F2))[sl];
#pragma unroll
            for (int q = 0; q < 8; q++) {
                float2 f = __half22float2(v[q]);
                acc.x += f.x; acc.y += f.y;
            }
        }
        if (e + 4 <= re) {
            int s[4]; __half2 v[4];
#pragma unroll
            for (int q = 0; q < 4; q++) s[q] = g_esrc[e + q];
#pragma unroll
            for (int q = 0; q < 4; q++)
                v[q] = ((const __half2*)(g_h2h + (size_t)s[q] * F2))[sl];
#pragma unroll
            for (int q = 0; q < 4; q++) {
                float2 f = __half22float2(v[q]);
                acc.x += f.x; acc.y += f.y;
            }
            e += 4;
        }
        for (; e < re; e++) {
            float2 f = __half22float2(((const __half2*)(g_h2h + (size_t)g_esrc[e] * F2))[sl]);
            acc.x += f.x; acc.y += f.y;
        }
        float2 o;
        o.x = fmaf(drow, acc.x, b2v.x);
        o.y = fmaf(drow, acc.y, b2v.y);
        ((float2*)(out + (size_t)row * F2))[sl] = o;
    }
}

// ---------------- launch ----------------
extern "C" void kernel_launch(void* const* d_in, const int* in_sizes, int n_in,
                              void* d_out, int out_size) {
    const float* x  = (const float*)d_in[0];
    const void*  ei = d_in[1];
    const float* W1 = (const float*)d_in[2];
    const float* b1 = (const float*)d_in[3];
    const float* W2 = (const float*)d_in[4];
    const float* b2 = (const float*)d_in[5];
    float* out = (float*)d_out;

    cudaStream_t s2;
    cudaStreamCreateWithFlags(&s2, cudaStreamNonBlocking);
    cudaEvent_t evScan, evG;
    cudaEventCreateWithFlags(&evScan, cudaEventDisableTiming);
    cudaEventCreateWithFlags(&evG, cudaEventDisableTiming);

    // main chain: CSR build (dis ready after scan)
    init_kernel<<<(N_NODES + 255) / 256, 256>>>(ei);
    count_kernel<<<(N_EDGES / 4 + 255) / 256, 256>>>(ei);
    scan_kernel<<<N_SCAN_BLK, SCAN_B>>>();
    cudaEventRecord(evScan, 0);

    // side stream: gemm1 (needs dis) overlaps csr_scatter
    cudaStreamWaitEvent(s2, evScan, 0);
    gemm1_kernel<<<(N_NODES + 63) / 64, 256, 0, s2>>>(x, W1);
    cudaEventRecord(evG, s2);

    csr_scatter_kernel<<<(N_EDGES / 2 + 255) / 256, 256>>>(ei);

    // join, then the two gather stages
    cudaStreamWaitEvent(0, evG, 0);
    agg1_mid_kernel<<<(N_NODES + A1_NODES - 1) / A1_NODES, 256>>>(b1, W2);
    agg2_kernel<<<A2_BLOCKS, 512>>>(b2, out);
}